// round 2
// baseline (speedup 1.0000x reference)
#include <cuda_runtime.h>
#include <cstdint>
#include <math.h>

// ---------------------------------------------------------------------------
// Scratch (static __device__ — no allocation allowed)
// ---------------------------------------------------------------------------
#define BATCH 128

__device__ unsigned g_a1[BATCH*32*32*4];    // conv1 out bits (128 ch)
__device__ unsigned g_a2[BATCH*16*16*4];    // conv2+pool out bits (128 ch)
__device__ unsigned g_a3[BATCH*16*16*8];    // conv3 out bits (256 ch)
__device__ unsigned g_a4[BATCH*8*8*8];      // conv4+pool out bits (256 ch)
__device__ unsigned g_a5[BATCH*8*8*16];     // conv5 out bits (512 ch)
__device__ float    g_h6[BATCH*4*4*512];    // conv6+pool+bn float out

__device__ unsigned g_wb2[9*4*128];         // [tap*CW+cw][Cout] layout
__device__ unsigned g_wb3[9*4*256];
__device__ unsigned g_wb4[9*8*256];
__device__ unsigned g_wb5[9*8*512];
__device__ unsigned g_wb6[9*16*512];

// ---------------------------------------------------------------------------
// Weight binarize+pack: w is HWIO (3,3,Cin,Cout). Output wb[(tap*CW+cw)*Cout+o]
// bit c%32 of word cw = (w[tap][cw*32+c][o] > 0)
// ---------------------------------------------------------------------------
__global__ void pack_w_kernel(const float* __restrict__ w, unsigned* __restrict__ wb,
                              int Cin, int Cout) {
    int o   = blockIdx.x % Cout;
    int tap = blockIdx.x / Cout;
    int c   = threadIdx.x;                  // blockDim.x == Cin (<=512)
    float v = w[(tap*Cin + c)*Cout + o];
    unsigned m = __ballot_sync(0xffffffffu, v > 0.f);
    if ((c & 31) == 0)
        wb[(tap*(Cin>>5) + (c>>5))*Cout + o] = m;
}

// ---------------------------------------------------------------------------
// conv1: float 3x3 SAME conv (Cin=3) + bias + relu + BN + sign -> packed bits
// Arithmetic chain chosen to mirror XLA-CPU (Eigen gebp): conv sum from 0 with
// sequential single-accumulator FMA, taps in (ky,kx,c) order (c fastest), bias
// added AFTER the conv sum, BN as separate mul-then-add (no FMA contraction).
// block = 128 threads (one per out channel), grid = (32 rows, 128 batch)
// ---------------------------------------------------------------------------
__global__ void conv1_kernel(const float* __restrict__ x, const float* __restrict__ w1,
                             const float* __restrict__ b1, const float* __restrict__ s1,
                             const float* __restrict__ bb1, unsigned* __restrict__ a1) {
    __shared__ float sm[3][34][3];          // rows y-1..y+1, x=-1..32, 3 ch
    const int b = blockIdx.y;
    const int y = blockIdx.x;
    const int o = threadIdx.x;

    for (int i = o; i < 3*34*3; i += 128) {
        int c  = i % 3;
        int t  = i / 3;
        int xx = t % 34 - 1;
        int ry = t / 34;
        int iy = y - 1 + ry;
        float v = 0.f;
        if ((unsigned)iy < 32u && (unsigned)xx < 32u)
            v = x[((b*32 + iy)*32 + xx)*3 + c];
        sm[ry][t % 34][c] = v;
    }
    __syncthreads();

    float wr[27];
#pragma unroll
    for (int k = 0; k < 27; k++) wr[k] = w1[k*128 + o];
    const float bias = b1[o], sc = s1[o], bb = bb1[o];

    for (int xx = 0; xx < 32; xx++) {
        float acc = 0.f;                    // conv sum starts at 0 (bias after)
#pragma unroll
        for (int ky = 0; ky < 3; ky++)
#pragma unroll
            for (int kx = 0; kx < 3; kx++)
#pragma unroll
                for (int c = 0; c < 3; c++)
                    acc = fmaf(sm[ky][xx+kx][c], wr[(ky*3+kx)*3+c], acc);
        float hpre = __fadd_rn(acc, bias);            // conv + b1
        float r    = fmaxf(hpre, 0.f);                // relu
        float h    = __fadd_rn(__fmul_rn(r, sc), bb); // BN: mul then add, no FMA
        unsigned m = __ballot_sync(0xffffffffu, h > 0.f);
        if ((o & 31) == 0)
            a1[((b*32 + y)*32 + xx)*4 + (o >> 5)] = m;
    }
}

// ---------------------------------------------------------------------------
// Generic binary conv: XNOR-popcount 3x3 SAME, optional fused 2x2 maxpool,
// relu + BN + (sign-pack | float out). All threshold math uses explicit
// mul-then-add in f32: integer operands => bit-identical to reference.
// block = Cout threads (1 per out channel), grid = (Hout*Wout, BATCH)
// act layout: [b][y][x][cw], wb layout: [(tap*CW+cw)][Cout]
// ---------------------------------------------------------------------------
template<int CW, bool POOL, bool FOUT>
__global__ void bconv_kernel(const unsigned* __restrict__ act,
                             const unsigned* __restrict__ wb,
                             const float* __restrict__ scale,
                             const float* __restrict__ bias,
                             unsigned* __restrict__ outb,
                             float* __restrict__ outf,
                             int Hin, int Win) {
    constexpr int R = POOL ? 4 : 3;
    __shared__ unsigned sm[R*R*CW];
    const int o    = threadIdx.x;
    const int Cout = blockDim.x;
    const int b    = blockIdx.y;
    const int Hout = POOL ? (Hin >> 1) : Hin;
    const int Wout = POOL ? (Win >> 1) : Win;
    const int py   = blockIdx.x / Wout;
    const int px   = blockIdx.x % Wout;
    const int iy0  = (POOL ? 2*py : py) - 1;
    const int ix0  = (POOL ? 2*px : px) - 1;

    for (int i = o; i < R*R*CW; i += Cout) {
        int cw = i % CW;
        int rx = (i / CW) % R;
        int ry = i / (CW*R);
        int iy = iy0 + ry, ix = ix0 + rx;
        unsigned v = 0;
        if ((unsigned)iy < (unsigned)Hin && (unsigned)ix < (unsigned)Win)
            v = act[((b*Hin + iy)*Win + ix)*CW + cw];
        sm[i] = v;
    }
    __syncthreads();

    bool rv[R], cv[R];
#pragma unroll
    for (int r = 0; r < R; r++) {
        rv[r] = (unsigned)(iy0 + r) < (unsigned)Hin;
        cv[r] = (unsigned)(ix0 + r) < (unsigned)Win;
    }

    float result;
    if constexpr (POOL) {
        int p00 = 0, p01 = 0, p10 = 0, p11 = 0;
#pragma unroll
        for (int cw = 0; cw < CW; cw++) {
            unsigned a[16];
#pragma unroll
            for (int r = 0; r < 16; r++) a[r] = sm[r*CW + cw];
#pragma unroll
            for (int ky = 0; ky < 3; ky++)
#pragma unroll
                for (int kx = 0; kx < 3; kx++) {
                    unsigned w = wb[((ky*3+kx)*CW + cw)*Cout + o];
                    if (rv[ky]   && cv[kx]  ) p00 += __popc(a[ ky   *4 + kx    ] ^ w);
                    if (rv[ky]   && cv[kx+1]) p01 += __popc(a[ ky   *4 + kx + 1] ^ w);
                    if (rv[ky+1] && cv[kx]  ) p10 += __popc(a[(ky+1)*4 + kx    ] ^ w);
                    if (rv[ky+1] && cv[kx+1]) p11 += __popc(a[(ky+1)*4 + kx + 1] ^ w);
                }
        }
        const int C = 32*CW;
        int nr0 = rv[0]+rv[1]+rv[2], nr1 = rv[1]+rv[2]+rv[3];
        int nc0 = cv[0]+cv[1]+cv[2], nc1 = cv[1]+cv[2]+cv[3];
        int s00 = nr0*nc0*C - 2*p00;
        int s01 = nr0*nc1*C - 2*p01;
        int s10 = nr1*nc0*C - 2*p10;
        int s11 = nr1*nc1*C - 2*p11;
        int m = max(max(max(s00, s01), max(s10, s11)), 0);   // relu ∘ maxpool
        result = __fadd_rn(__fmul_rn((float)m, scale[o]), bias[o]);
    } else {
        int p = 0;
#pragma unroll
        for (int cw = 0; cw < CW; cw++) {
#pragma unroll
            for (int t = 0; t < 9; t++) {
                if (rv[t/3] && cv[t%3]) {
                    unsigned w = wb[(t*CW + cw)*Cout + o];
                    p += __popc(sm[t*CW + cw] ^ w);
                }
            }
        }
        int n = (rv[0]+rv[1]+rv[2]) * (cv[0]+cv[1]+cv[2]);
        int s = max(n*32*CW - 2*p, 0);                       // relu
        result = __fadd_rn(__fmul_rn((float)s, scale[o]), bias[o]);
    }

    if constexpr (FOUT) {
        outf[((b*Hout + py)*Wout + px)*Cout + o] = result;
    } else {
        unsigned m = __ballot_sync(0xffffffffu, result > 0.f);
        if ((o & 31) == 0)
            outb[((b*Hout + py)*Wout + px)*(Cout >> 5) + (o >> 5)] = m;
    }
}

// ---------------------------------------------------------------------------
// Dense (512->10) on last axis + softmax. One warp per row (2048 rows).
// ---------------------------------------------------------------------------
__global__ void dense_softmax_kernel(const float* __restrict__ h,
                                     const float* __restrict__ W,
                                     const float* __restrict__ bd,
                                     float* __restrict__ out) {
    const int row  = blockIdx.x;
    const int lane = threadIdx.x;
    const float* hr = h + row*512;
    float acc[10];
#pragma unroll
    for (int j = 0; j < 10; j++) acc[j] = 0.f;
    for (int k = lane; k < 512; k += 32) {
        float v = hr[k];
#pragma unroll
        for (int j = 0; j < 10; j++) acc[j] = fmaf(v, W[k*10 + j], acc[j]);
    }
#pragma unroll
    for (int j = 0; j < 10; j++)
#pragma unroll
        for (int off = 16; off; off >>= 1)
            acc[j] += __shfl_xor_sync(0xffffffffu, acc[j], off);
    if (lane == 0) {
        float l[10], m = -1e30f;
#pragma unroll
        for (int j = 0; j < 10; j++) { l[j] = acc[j] + bd[j]; m = fmaxf(m, l[j]); }
        float s = 0.f;
#pragma unroll
        for (int j = 0; j < 10; j++) { l[j] = expf(l[j] - m); s += l[j]; }
        float inv = 1.f / s;
#pragma unroll
        for (int j = 0; j < 10; j++) out[row*10 + j] = l[j] * inv;
    }
}

// ---------------------------------------------------------------------------
// Launch
// ---------------------------------------------------------------------------
extern "C" void kernel_launch(void* const* d_in, const int* in_sizes, int n_in,
                              void* d_out, int out_size) {
    auto F = [&](int i) { return (const float*)d_in[i]; };
    const float *x = F(0), *w1 = F(1), *b1 = F(2);
    const float *w2, *w3, *w4, *w5, *w6;
    const float *s1, *bb1, *s2, *bb2, *s3, *bb3, *s4, *bb4, *s5, *bb5, *s6, *bb6;
    const float *dw, *db;

    if (in_sizes[3] == 3*3*128*128) {
        // setup_inputs() dict order: x,w1,b1,w2..w6,bn1s,bn1b,...,bn6b,dw,db
        w2 = F(3); w3 = F(4); w4 = F(5); w5 = F(6); w6 = F(7);
        s1 = F(8);  bb1 = F(9);  s2 = F(10); bb2 = F(11);
        s3 = F(12); bb3 = F(13); s4 = F(14); bb4 = F(15);
        s5 = F(16); bb5 = F(17); s6 = F(18); bb6 = F(19);
        dw = F(20); db = F(21);
    } else {
        // reference() signature order
        s1 = F(3);  bb1 = F(4);
        w2 = F(5);  s2 = F(6);  bb2 = F(7);
        w3 = F(8);  s3 = F(9);  bb3 = F(10);
        w4 = F(11); s4 = F(12); bb4 = F(13);
        w5 = F(14); s5 = F(15); bb5 = F(16);
        w6 = F(17); s6 = F(18); bb6 = F(19);
        dw = F(20); db = F(21);
    }

    unsigned *a1, *a2, *a3, *a4, *a5, *wb2, *wb3, *wb4, *wb5, *wb6;
    float* h6;
    cudaGetSymbolAddress((void**)&a1,  g_a1);
    cudaGetSymbolAddress((void**)&a2,  g_a2);
    cudaGetSymbolAddress((void**)&a3,  g_a3);
    cudaGetSymbolAddress((void**)&a4,  g_a4);
    cudaGetSymbolAddress((void**)&a5,  g_a5);
    cudaGetSymbolAddress((void**)&wb2, g_wb2);
    cudaGetSymbolAddress((void**)&wb3, g_wb3);
    cudaGetSymbolAddress((void**)&wb4, g_wb4);
    cudaGetSymbolAddress((void**)&wb5, g_wb5);
    cudaGetSymbolAddress((void**)&wb6, g_wb6);
    cudaGetSymbolAddress((void**)&h6,  g_h6);

    // Weight binarize + pack
    pack_w_kernel<<<9*128, 128>>>(w2, wb2, 128, 128);
    pack_w_kernel<<<9*256, 128>>>(w3, wb3, 128, 256);
    pack_w_kernel<<<9*256, 256>>>(w4, wb4, 256, 256);
    pack_w_kernel<<<9*512, 256>>>(w5, wb5, 256, 512);
    pack_w_kernel<<<9*512, 512>>>(w6, wb6, 512, 512);

    // conv1 (float) fused -> bits
    conv1_kernel<<<dim3(32, BATCH), 128>>>(x, w1, b1, s1, bb1, a1);

    // Binary pipeline
    bconv_kernel<4,  true,  false><<<dim3(16*16, BATCH), 128>>>(a1, wb2, s2, bb2, a2, nullptr, 32, 32);
    bconv_kernel<4,  false, false><<<dim3(16*16, BATCH), 256>>>(a2, wb3, s3, bb3, a3, nullptr, 16, 16);
    bconv_kernel<8,  true,  false><<<dim3(8*8,   BATCH), 256>>>(a3, wb4, s4, bb4, a4, nullptr, 16, 16);
    bconv_kernel<8,  false, false><<<dim3(8*8,   BATCH), 512>>>(a4, wb5, s5, bb5, a5, nullptr, 8, 8);
    bconv_kernel<16, true,  true ><<<dim3(4*4,   BATCH), 512>>>(a5, wb6, s6, bb6, nullptr, h6, 8, 8);

    // Dense + softmax
    dense_softmax_kernel<<<BATCH*4*4, 32>>>(h6, dw, db, (float*)d_out);
}

// round 3
// speedup vs baseline: 1.3570x; 1.3570x over previous
#include <cuda_runtime.h>
#include <cstdint>
#include <math.h>

#define BATCH 128

// ---------------------------------------------------------------------------
// Scratch (static __device__ — no allocation allowed)
// ---------------------------------------------------------------------------
__device__ unsigned g_a1[BATCH*32*32*4];    // conv1 out bits (128 ch)
__device__ unsigned g_a2[BATCH*16*16*4];    // conv2+pool out bits (128 ch)
__device__ unsigned g_a3[BATCH*16*16*8];    // conv3 out bits (256 ch)
__device__ unsigned g_a4[BATCH*8*8*8];      // conv4+pool out bits (256 ch)
__device__ unsigned g_a5[BATCH*8*8*16];     // conv5 out bits (512 ch)
__device__ float    g_h6[BATCH*4*4*512];    // conv6+pool+bn float out

__device__ unsigned g_wb2[9*4*128];         // [(tap*CW+cw)*Cout + o]
__device__ unsigned g_wb3[9*4*256];
__device__ unsigned g_wb4[9*8*256];
__device__ unsigned g_wb5[9*8*512];
__device__ unsigned g_wb6[9*16*512];

// ---------------------------------------------------------------------------
// Merged weight pack: one kernel for all 5 binary layers, coalesced loads.
// Warp task = (layer, tap, cw, o-group). Lane o builds its own 32-bit word
// over 32 channel iterations (each iteration is a coalesced 128B load).
// ---------------------------------------------------------------------------
struct PackArgs {
    const float* w[5];
    unsigned*    wb[5];
    int Cin[5], Cout[5];
    int wstart[6];      // warp-task prefix sums
};

__global__ void pack_all_kernel(PackArgs pa) {
    int warp = (blockIdx.x * blockDim.x + threadIdx.x) >> 5;
    int lane = threadIdx.x & 31;
    if (warp >= pa.wstart[5]) return;
    int l = 0;
    while (l < 4 && warp >= pa.wstart[l+1]) l++;
    int rel  = warp - pa.wstart[l];
    int Cin  = pa.Cin[l], Cout = pa.Cout[l];
    int OG   = Cout >> 5;
    int CWl  = Cin >> 5;
    int og   = rel % OG;
    int t2   = rel / OG;
    int cw   = t2 % CWl;
    int tap  = t2 / CWl;
    int o    = og*32 + lane;
    const float* wsrc = pa.w[l] + (size_t)(tap*Cin + cw*32)*Cout + o;
    unsigned word = 0;
#pragma unroll
    for (int j = 0; j < 32; j++)
        if (wsrc[(size_t)j*Cout] > 0.f) word |= (1u << j);
    pa.wb[l][(tap*CWl + cw)*Cout + o] = word;
}

// ---------------------------------------------------------------------------
// conv1: float 3x3 SAME conv (Cin=3) + bias + relu + BN + sign -> packed bits
// Arithmetic chain EXACT as validated in R2 (do not touch).
// ---------------------------------------------------------------------------
__global__ void conv1_kernel(const float* __restrict__ x, const float* __restrict__ w1,
                             const float* __restrict__ b1, const float* __restrict__ s1,
                             const float* __restrict__ bb1, unsigned* __restrict__ a1) {
    __shared__ float sm[3][34][3];
    const int b = blockIdx.y;
    const int y = blockIdx.x;
    const int o = threadIdx.x;

    for (int i = o; i < 3*34*3; i += 128) {
        int c  = i % 3;
        int t  = i / 3;
        int xx = t % 34 - 1;
        int ry = t / 34;
        int iy = y - 1 + ry;
        float v = 0.f;
        if ((unsigned)iy < 32u && (unsigned)xx < 32u)
            v = x[((b*32 + iy)*32 + xx)*3 + c];
        sm[ry][t % 34][c] = v;
    }
    __syncthreads();

    float wr[27];
#pragma unroll
    for (int k = 0; k < 27; k++) wr[k] = w1[k*128 + o];
    const float bias = b1[o], sc = s1[o], bb = bb1[o];

    for (int xx = 0; xx < 32; xx++) {
        float acc = 0.f;
#pragma unroll
        for (int ky = 0; ky < 3; ky++)
#pragma unroll
            for (int kx = 0; kx < 3; kx++)
#pragma unroll
                for (int c = 0; c < 3; c++)
                    acc = fmaf(sm[ky][xx+kx][c], wr[(ky*3+kx)*3+c], acc);
        float hpre = __fadd_rn(acc, bias);
        float r    = fmaxf(hpre, 0.f);
        float h    = __fadd_rn(__fmul_rn(r, sc), bb);
        unsigned m = __ballot_sync(0xffffffffu, h > 0.f);
        if ((o & 31) == 0)
            a1[((b*32 + y)*32 + xx)*4 + (o >> 5)] = m;
    }
}

// ---------------------------------------------------------------------------
// Binary conv v2: row-tiled, zero-halo smem, branch-free inner loop with
// padding-popcount correction. Each block handles one output row tile of
// 8 conv columns (= 4 pooled or 8 plain outputs), cw-outer loop with 9
// weight regs, activation row cached in registers per cw.
// Thread = output channel o.
// ---------------------------------------------------------------------------
template<int CW, int HIN, int WIN, bool POOL, bool FOUT>
__global__ void bconv2_kernel(const unsigned* __restrict__ act,
                              const unsigned* __restrict__ wb,
                              const float* __restrict__ scale,
                              const float* __restrict__ bias,
                              unsigned* __restrict__ outb,
                              float* __restrict__ outf) {
    constexpr int ROWS   = POOL ? 4 : 3;
    constexpr int WOUT   = POOL ? WIN/2 : WIN;
    constexpr int HOUT   = POOL ? HIN/2 : HIN;
    constexpr int OPT    = POOL ? 4 : 8;        // outputs per tile
    constexpr int NTILES = WOUT / OPT;
    constexpr int PACC   = POOL ? 4 : 2;        // positions per step
    constexpr int CBITS  = 32*CW;

    __shared__ unsigned sm[ROWS][10][CW];

    const int o    = threadIdx.x;
    const int Cout = blockDim.x;
    const int b    = blockIdx.y;
    const int py   = blockIdx.x / NTILES;       // output row
    const int tile = blockIdx.x % NTILES;
    const int cx0  = tile * 8;                  // first conv col of tile
    const int iy0  = (POOL ? 2*py : py) - 1;

    // fill smem with zero halo
    for (int i = o; i < ROWS*10*CW; i += Cout) {
        int cw = i % CW;
        int c  = (i/CW) % 10;
        int r  = i/(CW*10);
        int iy = iy0 + r, ix = cx0 - 1 + c;
        unsigned v = 0;
        if ((unsigned)iy < (unsigned)HIN && (unsigned)ix < (unsigned)WIN)
            v = act[((b*HIN + iy)*WIN + ix)*CW + cw];
        sm[r][c][cw] = v;
    }
    __syncthreads();

    // edge classification (block-uniform)
    const bool Aedge = POOL ? (py == 0)            : (py == 0);        // top conv row has ky=0 invalid
    const bool Bedge = POOL ? (py == HIN/2 - 1)    : (py == HIN - 1);  // bottom conv row has ky=2 invalid
    // (non-pool uses Aedge=top, Bedge=bottom on the single row class)

    int p[4][PACC];
#pragma unroll
    for (int s = 0; s < 4; s++)
#pragma unroll
        for (int q = 0; q < PACC; q++) p[s][q] = 0;

    int cRA=0, cRB=0, cA0=0, cA2=0, cB0=0, cB2=0;

    const unsigned* wbo = wb + o;

#pragma unroll 1
    for (int cw = 0; cw < CW; cw++) {
        unsigned w[9];
#pragma unroll
        for (int t = 0; t < 9; t++) w[t] = wbo[(t*CW + cw)*Cout];

        int pt[9];
#pragma unroll
        for (int t = 0; t < 9; t++) pt[t] = __popc(w[t]);

        if (POOL) {
            if (Aedge) cRA += pt[0]+pt[1]+pt[2];
            if (Bedge) cRB += pt[6]+pt[7]+pt[8];
            cA0 += (Aedge?0:pt[0]) + pt[3] + pt[6];
            cA2 += (Aedge?0:pt[2]) + pt[5] + pt[8];
            cB0 += pt[0] + pt[3] + (Bedge?0:pt[6]);
            cB2 += pt[2] + pt[5] + (Bedge?0:pt[8]);
        } else {
            if (Aedge) cRA += pt[0]+pt[1]+pt[2];
            if (Bedge) cRA += pt[6]+pt[7]+pt[8];
            cA0 += (Aedge?0:pt[0]) + pt[3] + (Bedge?0:pt[6]);
            cA2 += (Aedge?0:pt[2]) + pt[5] + (Bedge?0:pt[8]);
        }

        // activation row slab into registers (broadcast LDS)
        unsigned a[ROWS][10];
#pragma unroll
        for (int r = 0; r < ROWS; r++)
#pragma unroll
            for (int c = 0; c < 10; c++) a[r][c] = sm[r][c][cw];

#pragma unroll
        for (int s = 0; s < 4; s++) {
            const int base = 2*s;
#pragma unroll
            for (int ky = 0; ky < 3; ky++)
#pragma unroll
                for (int kx = 0; kx < 3; kx++) {
                    unsigned ww = w[ky*3+kx];
                    p[s][0] += __popc(a[ky][base+kx]   ^ ww);
                    p[s][1] += __popc(a[ky][base+kx+1] ^ ww);
                    if (POOL) {
                        p[s][2] += __popc(a[ky+1][base+kx]   ^ ww);
                        p[s][3] += __popc(a[ky+1][base+kx+1] ^ ww);
                    }
                }
        }
    }

    const float sc = scale[o], bb = bias[o];

    if (POOL) {
        const int nrA = Aedge ? 2 : 3;
        const int nrB = Bedge ? 2 : 3;
#pragma unroll
        for (int s = 0; s < 4; s++) {
            int px  = tile*4 + s;
            int cxL = 2*px, cxR = 2*px + 1;
            int ncL = (cxL == 0)      ? 2 : 3;
            int ncR = (cxR == WIN-1)  ? 2 : 3;
            int corrLA = cRA + ((cxL == 0)     ? cA0 : 0);
            int corrRA = cRA + ((cxR == WIN-1) ? cA2 : 0);
            int corrLB = cRB + ((cxL == 0)     ? cB0 : 0);
            int corrRB = cRB + ((cxR == WIN-1) ? cB2 : 0);
            int s00 = nrA*ncL*CBITS - 2*p[s][0] + 2*corrLA;
            int s01 = nrA*ncR*CBITS - 2*p[s][1] + 2*corrRA;
            int s10 = nrB*ncL*CBITS - 2*p[s][2] + 2*corrLB;
            int s11 = nrB*ncR*CBITS - 2*p[s][3] + 2*corrRB;
            int m = max(max(s00, s01), max(s10, s11));
            m = max(m, 0);                                   // relu ∘ maxpool
            float res = __fadd_rn(__fmul_rn((float)m, sc), bb);
            if (FOUT) {
                outf[((b*HOUT + py)*WOUT + px)*Cout + o] = res;
            } else {
                unsigned msk = __ballot_sync(0xffffffffu, res > 0.f);
                if ((o & 31) == 0)
                    outb[((b*HOUT + py)*WOUT + px)*(Cout >> 5) + (o >> 5)] = msk;
            }
        }
    } else {
        const int nr = 3 - (Aedge?1:0) - (Bedge?1:0);
#pragma unroll
        for (int s = 0; s < 4; s++) {
#pragma unroll
            for (int dx = 0; dx < 2; dx++) {
                int x  = cx0 + 2*s + dx;
                int nc = (x == 0 || x == WIN-1) ? 2 : 3;
                int corr = cRA + ((x == 0) ? cA0 : 0) + ((x == WIN-1) ? cA2 : 0);
                int sv = nr*nc*CBITS - 2*p[s][dx] + 2*corr;
                sv = max(sv, 0);                             // relu
                float res = __fadd_rn(__fmul_rn((float)sv, sc), bb);
                if (FOUT) {
                    outf[((b*HOUT + py)*WOUT + x)*Cout + o] = res;
                } else {
                    unsigned msk = __ballot_sync(0xffffffffu, res > 0.f);
                    if ((o & 31) == 0)
                        outb[((b*HOUT + py)*WOUT + x)*(Cout >> 5) + (o >> 5)] = msk;
                }
            }
        }
    }
}

// ---------------------------------------------------------------------------
// Dense (512->10) on last axis + softmax. One warp per row (2048 rows).
// ---------------------------------------------------------------------------
__global__ void dense_softmax_kernel(const float* __restrict__ h,
                                     const float* __restrict__ W,
                                     const float* __restrict__ bd,
                                     float* __restrict__ out) {
    const int row  = blockIdx.x;
    const int lane = threadIdx.x;
    const float* hr = h + row*512;
    float acc[10];
#pragma unroll
    for (int j = 0; j < 10; j++) acc[j] = 0.f;
    for (int k = lane; k < 512; k += 32) {
        float v = hr[k];
#pragma unroll
        for (int j = 0; j < 10; j++) acc[j] = fmaf(v, W[k*10 + j], acc[j]);
    }
#pragma unroll
    for (int j = 0; j < 10; j++)
#pragma unroll
        for (int off = 16; off; off >>= 1)
            acc[j] += __shfl_xor_sync(0xffffffffu, acc[j], off);
    if (lane == 0) {
        float l[10], m = -1e30f;
#pragma unroll
        for (int j = 0; j < 10; j++) { l[j] = acc[j] + bd[j]; m = fmaxf(m, l[j]); }
        float s = 0.f;
#pragma unroll
        for (int j = 0; j < 10; j++) { l[j] = expf(l[j] - m); s += l[j]; }
        float inv = 1.f / s;
#pragma unroll
        for (int j = 0; j < 10; j++) out[row*10 + j] = l[j] * inv;
    }
}

// ---------------------------------------------------------------------------
// Launch
// ---------------------------------------------------------------------------
extern "C" void kernel_launch(void* const* d_in, const int* in_sizes, int n_in,
                              void* d_out, int out_size) {
    auto F = [&](int i) { return (const float*)d_in[i]; };
    const float *x = F(0), *w1 = F(1), *b1 = F(2);
    const float *w2, *w3, *w4, *w5, *w6;
    const float *s1, *bb1, *s2, *bb2, *s3, *bb3, *s4, *bb4, *s5, *bb5, *s6, *bb6;
    const float *dw, *db;

    if (in_sizes[3] == 3*3*128*128) {
        w2 = F(3); w3 = F(4); w4 = F(5); w5 = F(6); w6 = F(7);
        s1 = F(8);  bb1 = F(9);  s2 = F(10); bb2 = F(11);
        s3 = F(12); bb3 = F(13); s4 = F(14); bb4 = F(15);
        s5 = F(16); bb5 = F(17); s6 = F(18); bb6 = F(19);
        dw = F(20); db = F(21);
    } else {
        s1 = F(3);  bb1 = F(4);
        w2 = F(5);  s2 = F(6);  bb2 = F(7);
        w3 = F(8);  s3 = F(9);  bb3 = F(10);
        w4 = F(11); s4 = F(12); bb4 = F(13);
        w5 = F(14); s5 = F(15); bb5 = F(16);
        w6 = F(17); s6 = F(18); bb6 = F(19);
        dw = F(20); db = F(21);
    }

    unsigned *a1, *a2, *a3, *a4, *a5, *wb2, *wb3, *wb4, *wb5, *wb6;
    float* h6;
    cudaGetSymbolAddress((void**)&a1,  g_a1);
    cudaGetSymbolAddress((void**)&a2,  g_a2);
    cudaGetSymbolAddress((void**)&a3,  g_a3);
    cudaGetSymbolAddress((void**)&a4,  g_a4);
    cudaGetSymbolAddress((void**)&a5,  g_a5);
    cudaGetSymbolAddress((void**)&wb2, g_wb2);
    cudaGetSymbolAddress((void**)&wb3, g_wb3);
    cudaGetSymbolAddress((void**)&wb4, g_wb4);
    cudaGetSymbolAddress((void**)&wb5, g_wb5);
    cudaGetSymbolAddress((void**)&wb6, g_wb6);
    cudaGetSymbolAddress((void**)&h6,  g_h6);

    // Merged pack: warp tasks per layer = 9*(Cin/32)*(Cout/32)
    PackArgs pa;
    pa.w[0]=w2; pa.w[1]=w3; pa.w[2]=w4; pa.w[3]=w5; pa.w[4]=w6;
    pa.wb[0]=wb2; pa.wb[1]=wb3; pa.wb[2]=wb4; pa.wb[3]=wb5; pa.wb[4]=wb6;
    int cins[5]  = {128,128,256,256,512};
    int couts[5] = {128,256,256,512,512};
    int acc = 0;
    for (int l = 0; l < 5; l++) {
        pa.Cin[l] = cins[l]; pa.Cout[l] = couts[l];
        pa.wstart[l] = acc;
        acc += 9*(cins[l]>>5)*(couts[l]>>5);
    }
    pa.wstart[5] = acc;                 // 4464 warp tasks
    int pack_blocks = (acc*32 + 255)/256;
    pack_all_kernel<<<pack_blocks, 256>>>(pa);

    conv1_kernel<<<dim3(32, BATCH), 128>>>(x, w1, b1, s1, bb1, a1);

    bconv2_kernel<4, 32, 32, true,  false><<<dim3(64, BATCH), 128>>>(a1, wb2, s2, bb2, a2, nullptr);
    bconv2_kernel<4, 16, 16, false, false><<<dim3(32, BATCH), 256>>>(a2, wb3, s3, bb3, a3, nullptr);
    bconv2_kernel<8, 16, 16, true,  false><<<dim3(16, BATCH), 256>>>(a3, wb4, s4, bb4, a4, nullptr);
    bconv2_kernel<8, 8,  8,  false, false><<<dim3(8,  BATCH), 512>>>(a4, wb5, s5, bb5, a5, nullptr);
    bconv2_kernel<16,8,  8,  true,  true ><<<dim3(4,  BATCH), 512>>>(a5, wb6, s6, bb6, nullptr, h6);

    dense_softmax_kernel<<<BATCH*4*4, 32>>>(h6, dw, db, (float*)d_out);
}

// round 7
// speedup vs baseline: 2.0520x; 1.5122x over previous
#include <cuda_runtime.h>
#include <cstdint>
#include <math.h>

#define BATCH 128

// ---------------------------------------------------------------------------
// Scratch (static __device__ — no allocation allowed)
// ---------------------------------------------------------------------------
__device__ unsigned g_a1[BATCH*32*32*4];    // conv1 out bits (128 ch)
__device__ unsigned g_a2[BATCH*16*16*4];    // conv2+pool out bits (128 ch)
__device__ unsigned g_a3[BATCH*16*16*8];    // conv3 out bits (256 ch)
__device__ unsigned g_a4[BATCH*8*8*8];      // conv4+pool out bits (256 ch)
__device__ unsigned g_a5[BATCH*8*8*16];     // conv5 out bits (512 ch)
__device__ float    g_h6[BATCH*4*4*512];    // conv6+pool+bn float out

__device__ unsigned g_wb2[9*4*128];         // [(tap*CW+cw)*Cout + o]
__device__ unsigned g_wb3[9*4*256];
__device__ unsigned g_wb4[9*8*256];
__device__ unsigned g_wb5[9*8*512];
__device__ unsigned g_wb6[9*16*512];

// per-channel edge-correction sums: 8 ints per output channel per layer
// layout per layer: [k][Cout], k: 0=sumT 1=sumB 2=sumL 3=sumR 4=pt0 5=pt2 6=pt6 7=pt8
__device__ int g_corr[8*(128+256+256+512+512)];

// ---------------------------------------------------------------------------
// LOP3 helpers (full-adder sum / majority)
// ---------------------------------------------------------------------------
__device__ __forceinline__ unsigned lop3_sum(unsigned a, unsigned b, unsigned c) {
    unsigned r;
    asm("lop3.b32 %0, %1, %2, %3, 0x96;" : "=r"(r) : "r"(a), "r"(b), "r"(c));
    return r;
}
__device__ __forceinline__ unsigned lop3_maj(unsigned a, unsigned b, unsigned c) {
    unsigned r;
    asm("lop3.b32 %0, %1, %2, %3, 0xE8;" : "=r"(r) : "r"(a), "r"(b), "r"(c));
    return r;
}

// ---------------------------------------------------------------------------
// Merged weight pack (unchanged from R3)
// ---------------------------------------------------------------------------
struct PackArgs {
    const float* w[5];
    unsigned*    wb[5];
    int Cin[5], Cout[5];
    int wstart[6];
};

__global__ void pack_all_kernel(PackArgs pa) {
    int warp = (blockIdx.x * blockDim.x + threadIdx.x) >> 5;
    int lane = threadIdx.x & 31;
    if (warp >= pa.wstart[5]) return;
    int l = 0;
    while (l < 4 && warp >= pa.wstart[l+1]) l++;
    int rel  = warp - pa.wstart[l];
    int Cin  = pa.Cin[l], Cout = pa.Cout[l];
    int OG   = Cout >> 5;
    int CWl  = Cin >> 5;
    int og   = rel % OG;
    int t2   = rel / OG;
    int cw   = t2 % CWl;
    int tap  = t2 / CWl;
    int o    = og*32 + lane;
    const float* wsrc = pa.w[l] + (size_t)(tap*Cin + cw*32)*Cout + o;
    unsigned word = 0;
#pragma unroll
    for (int j = 0; j < 32; j++)
        if (wsrc[(size_t)j*Cout] > 0.f) word |= (1u << j);
    pa.wb[l][(tap*CWl + cw)*Cout + o] = word;
}

// ---------------------------------------------------------------------------
// Edge-correction precompute: one thread per (layer, o)
// ---------------------------------------------------------------------------
struct CorrArgs {
    const unsigned* wb[5];
    int CW[5], Cout[5];
    int obase[6], cbase[5];
};

__global__ void corr_kernel(CorrArgs ca, int* corr) {
    int g = blockIdx.x * blockDim.x + threadIdx.x;
    if (g >= ca.obase[5]) return;
    int l = 0;
    while (l < 4 && g >= ca.obase[l+1]) l++;
    int o    = g - ca.obase[l];
    int CWl  = ca.CW[l], Cout = ca.Cout[l];
    const unsigned* wbo = ca.wb[l] + o;
    int sT=0, sB=0, sL=0, sR=0, c0=0, c2=0, c6=0, c8=0;
    for (int cw = 0; cw < CWl; cw++) {
        int pt[9];
#pragma unroll
        for (int t = 0; t < 9; t++) pt[t] = __popc(wbo[(t*CWl + cw)*Cout]);
        sT += pt[0]+pt[1]+pt[2];  sB += pt[6]+pt[7]+pt[8];
        sL += pt[0]+pt[3]+pt[6];  sR += pt[2]+pt[5]+pt[8];
        c0 += pt[0]; c2 += pt[2]; c6 += pt[6]; c8 += pt[8];
    }
    int* dst = corr + ca.cbase[l];
    dst[0*Cout+o]=sT; dst[1*Cout+o]=sB; dst[2*Cout+o]=sL; dst[3*Cout+o]=sR;
    dst[4*Cout+o]=c0; dst[5*Cout+o]=c2; dst[6*Cout+o]=c6; dst[7*Cout+o]=c8;
}

// ---------------------------------------------------------------------------
// conv1: float conv + bias + relu + BN + sign -> bits. EXACT chain from R2 —
// do not touch (bit-exactness feeds the chaotic binary pipeline).
// ---------------------------------------------------------------------------
__global__ void conv1_kernel(const float* __restrict__ x, const float* __restrict__ w1,
                             const float* __restrict__ b1, const float* __restrict__ s1,
                             const float* __restrict__ bb1, unsigned* __restrict__ a1) {
    __shared__ float sm[3][34][3];
    const int b = blockIdx.y;
    const int y = blockIdx.x;
    const int o = threadIdx.x;

    for (int i = o; i < 3*34*3; i += 128) {
        int c  = i % 3;
        int t  = i / 3;
        int xx = t % 34 - 1;
        int ry = t / 34;
        int iy = y - 1 + ry;
        float v = 0.f;
        if ((unsigned)iy < 32u && (unsigned)xx < 32u)
            v = x[((b*32 + iy)*32 + xx)*3 + c];
        sm[ry][t % 34][c] = v;
    }
    __syncthreads();

    float wr[27];
#pragma unroll
    for (int k = 0; k < 27; k++) wr[k] = w1[k*128 + o];
    const float bias = b1[o], sc = s1[o], bb = bb1[o];

    for (int xx = 0; xx < 32; xx++) {
        float acc = 0.f;
#pragma unroll
        for (int ky = 0; ky < 3; ky++)
#pragma unroll
            for (int kx = 0; kx < 3; kx++)
#pragma unroll
                for (int c = 0; c < 3; c++)
                    acc = fmaf(sm[ky][xx+kx][c], wr[(ky*3+kx)*3+c], acc);
        float hpre = __fadd_rn(acc, bias);
        float r    = fmaxf(hpre, 0.f);
        float h    = __fadd_rn(__fmul_rn(r, sc), bb);
        unsigned m = __ballot_sync(0xffffffffu, h > 0.f);
        if ((o & 31) == 0)
            a1[((b*32 + y)*32 + xx)*4 + (o >> 5)] = m;
    }
}

// ---------------------------------------------------------------------------
// Binary conv v3: CSA (ones) + weight-2 carry popcount, balanced ALU/POPC.
// 8 positions per thread. POOL: 2 pooled outputs (4 conv cols). nonPOOL: 8 cols.
// grid = (HOUT*NT, BATCH, COUT/BT), block = BT threads (one per out channel).
// ---------------------------------------------------------------------------
template<int CW, int HIN, int WIN, int COUT, int BT, bool POOL, bool FOUT>
__global__ __launch_bounds__(BT)
void bconv3_kernel(const unsigned* __restrict__ act,
                   const unsigned* __restrict__ wb,
                   const float* __restrict__ scale,
                   const float* __restrict__ bias,
                   const int* __restrict__ corr,
                   unsigned* __restrict__ outb,
                   float* __restrict__ outf) {
    constexpr int HOUT  = POOL ? HIN/2 : HIN;
    constexpr int WOUT  = POOL ? WIN/2 : WIN;
    constexpr int OPT   = POOL ? 2 : 8;        // x-outputs per tile
    constexpr int NT    = WOUT / OPT;
    constexpr int ROWS  = POOL ? 4 : 3;
    constexpr int COLS  = POOL ? 6 : 10;
    constexpr int NPOS  = 8;
    constexpr int CBITS = 32*CW;

    __shared__ unsigned sm[ROWS][COLS][CW];

    const int tid  = threadIdx.x;
    const int o    = blockIdx.z*BT + tid;
    const int b    = blockIdx.y;
    const int py   = blockIdx.x / NT;
    const int tile = blockIdx.x % NT;
    const int cx0  = tile * (POOL ? 4 : 8);
    const int iy0  = (POOL ? 2*py : py) - 1;

    // zero-halo smem fill
    for (int i = tid; i < ROWS*COLS*CW; i += BT) {
        int cw = i % CW;
        int c  = (i/CW) % COLS;
        int r  = i/(CW*COLS);
        int iy = iy0 + r, ix = cx0 - 1 + c;
        unsigned v = 0;
        if ((unsigned)iy < (unsigned)HIN && (unsigned)ix < (unsigned)WIN)
            v = act[((b*HIN + iy)*WIN + ix)*CW + cw];
        sm[r][c][cw] = v;
    }
    __syncthreads();

    // precomputed edge sums (L1-hot, 8 LDG)
    const int sT  = corr[0*COUT+o], sB  = corr[1*COUT+o];
    const int sL  = corr[2*COUT+o], sR  = corr[3*COUT+o];
    const int pc0 = corr[4*COUT+o], pc2 = corr[5*COUT+o];
    const int pc6 = corr[6*COUT+o], pc8 = corr[7*COUT+o];

    unsigned ones[NPOS], pend8[NPOS];
    int p2[NPOS];
#pragma unroll
    for (int p = 0; p < NPOS; p++) { ones[p] = 0u; p2[p] = 0; }

    const unsigned* wbo = wb + o;

#pragma unroll 1
    for (int cw2 = 0; cw2 < CW; cw2 += 2) {
#pragma unroll
        for (int half = 0; half < 2; half++) {
            const int cw = cw2 + half;
            unsigned w[9];
#pragma unroll
            for (int t = 0; t < 9; t++) w[t] = wbo[(t*CW + cw)*COUT];
            unsigned A[ROWS][COLS];
#pragma unroll
            for (int r = 0; r < ROWS; r++)
#pragma unroll
                for (int c = 0; c < COLS; c++) A[r][c] = sm[r][c][cw];

#pragma unroll
            for (int p = 0; p < NPOS; p++) {
                const int br = POOL ? ((p>>1)&1) : 0;             // qy
                const int bc = POOL ? (((p>>2)<<1) + (p&1)) : p;  // 2s+qx | x
                unsigned x[9];
#pragma unroll
                for (int ky = 0; ky < 3; ky++)
#pragma unroll
                    for (int kx = 0; kx < 3; kx++)
                        x[ky*3+kx] = A[br+ky][bc+kx] ^ w[ky*3+kx];
#pragma unroll
                for (int q = 0; q < 4; q++) {
                    unsigned cy = lop3_maj(ones[p], x[2*q], x[2*q+1]);
                    ones[p]     = lop3_sum(ones[p], x[2*q], x[2*q+1]);
                    p2[p] += __popc(cy);
                }
                if (half == 0) {
                    pend8[p] = x[8];
                } else {
                    unsigned cy = lop3_maj(ones[p], pend8[p], x[8]);
                    ones[p]     = lop3_sum(ones[p], pend8[p], x[8]);
                    p2[p] += __popc(cy);
                }
            }
        }
    }

    const float sc = scale[o], bb = bias[o];

    if (POOL) {
#pragma unroll
        for (int s = 0; s < 2; s++) {
            int m = 0;   // relu folded: max starts at 0
#pragma unroll
            for (int qy = 0; qy < 2; qy++)
#pragma unroll
                for (int qx = 0; qx < 2; qx++) {
                    int p  = s*4 + qy*2 + qx;
                    int cr = 2*py + qy;
                    int cc = cx0 + 2*s + qx;
                    int tI = (cr == 0), bI = (cr == HIN-1);
                    int lI = (cc == 0), rI = (cc == WIN-1);
                    int cor = (tI?sT:0) + (bI?sB:0) + (lI?sL:0) + (rI?sR:0)
                            - ((tI&&lI)?pc0:0) - ((tI&&rI)?pc2:0)
                            - ((bI&&lI)?pc6:0) - ((bI&&rI)?pc8:0);
                    int nv   = (3-tI-bI)*(3-lI-rI);
                    int ptot = __popc(ones[p]) + 2*p2[p];
                    int sv   = nv*CBITS - 2*ptot + 2*cor;
                    m = max(m, sv);
                }
            float res = __fadd_rn(__fmul_rn((float)m, sc), bb);
            int px = tile*2 + s;
            if (FOUT) {
                outf[((b*HOUT + py)*WOUT + px)*COUT + o] = res;
            } else {
                unsigned msk = __ballot_sync(0xffffffffu, res > 0.f);
                if ((tid & 31) == 0)
                    outb[((b*HOUT + py)*WOUT + px)*(COUT >> 5) + (o >> 5)] = msk;
            }
        }
    } else {
#pragma unroll
        for (int p = 0; p < NPOS; p++) {
            int cr = py;
            int cc = cx0 + p;
            int tI = (cr == 0), bI = (cr == HIN-1);
            int lI = (cc == 0), rI = (cc == WIN-1);
            int cor = (tI?sT:0) + (bI?sB:0) + (lI?sL:0) + (rI?sR:0)
                    - ((tI&&lI)?pc0:0) - ((tI&&rI)?pc2:0)
                    - ((bI&&lI)?pc6:0) - ((bI&&rI)?pc8:0);
            int nv   = (3-tI-bI)*(3-lI-rI);
            int ptot = __popc(ones[p]) + 2*p2[p];
            int sv   = nv*CBITS - 2*ptot + 2*cor;
            sv = max(sv, 0);
            float res = __fadd_rn(__fmul_rn((float)sv, sc), bb);
            if (FOUT) {
                outf[((b*HOUT + py)*WOUT + cc)*COUT + o] = res;
            } else {
                unsigned msk = __ballot_sync(0xffffffffu, res > 0.f);
                if ((tid & 31) == 0)
                    outb[((b*HOUT + py)*WOUT + cc)*(COUT >> 5) + (o >> 5)] = msk;
            }
        }
    }
}

// ---------------------------------------------------------------------------
// Dense (512->10) + softmax. One warp per row.
// ---------------------------------------------------------------------------
__global__ void dense_softmax_kernel(const float* __restrict__ h,
                                     const float* __restrict__ W,
                                     const float* __restrict__ bd,
                                     float* __restrict__ out) {
    const int row  = blockIdx.x;
    const int lane = threadIdx.x;
    const float* hr = h + row*512;
    float acc[10];
#pragma unroll
    for (int j = 0; j < 10; j++) acc[j] = 0.f;
    for (int k = lane; k < 512; k += 32) {
        float v = hr[k];
#pragma unroll
        for (int j = 0; j < 10; j++) acc[j] = fmaf(v, W[k*10 + j], acc[j]);
    }
#pragma unroll
    for (int j = 0; j < 10; j++)
#pragma unroll
        for (int off = 16; off; off >>= 1)
            acc[j] += __shfl_xor_sync(0xffffffffu, acc[j], off);
    if (lane == 0) {
        float l[10], m = -1e30f;
#pragma unroll
        for (int j = 0; j < 10; j++) { l[j] = acc[j] + bd[j]; m = fmaxf(m, l[j]); }
        float s = 0.f;
#pragma unroll
        for (int j = 0; j < 10; j++) { l[j] = expf(l[j] - m); s += l[j]; }
        float inv = 1.f / s;
#pragma unroll
        for (int j = 0; j < 10; j++) out[row*10 + j] = l[j] * inv;
    }
}

// ---------------------------------------------------------------------------
// Launch
// ---------------------------------------------------------------------------
extern "C" void kernel_launch(void* const* d_in, const int* in_sizes, int n_in,
                              void* d_out, int out_size) {
    auto F = [&](int i) { return (const float*)d_in[i]; };
    const float *x = F(0), *w1 = F(1), *b1 = F(2);
    const float *w2, *w3, *w4, *w5, *w6;
    const float *s1, *bb1, *s2, *bb2, *s3, *bb3, *s4, *bb4, *s5, *bb5, *s6, *bb6;
    const float *dw, *db;

    if (in_sizes[3] == 3*3*128*128) {
        w2 = F(3); w3 = F(4); w4 = F(5); w5 = F(6); w6 = F(7);
        s1 = F(8);  bb1 = F(9);  s2 = F(10); bb2 = F(11);
        s3 = F(12); bb3 = F(13); s4 = F(14); bb4 = F(15);
        s5 = F(16); bb5 = F(17); s6 = F(18); bb6 = F(19);
        dw = F(20); db = F(21);
    } else {
        s1 = F(3);  bb1 = F(4);
        w2 = F(5);  s2 = F(6);  bb2 = F(7);
        w3 = F(8);  s3 = F(9);  bb3 = F(10);
        w4 = F(11); s4 = F(12); bb4 = F(13);
        w5 = F(14); s5 = F(15); bb5 = F(16);
        w6 = F(17); s6 = F(18); bb6 = F(19);
        dw = F(20); db = F(21);
    }

    unsigned *a1, *a2, *a3, *a4, *a5, *wb2, *wb3, *wb4, *wb5, *wb6;
    float* h6;
    int* corr;
    cudaGetSymbolAddress((void**)&a1,  g_a1);
    cudaGetSymbolAddress((void**)&a2,  g_a2);
    cudaGetSymbolAddress((void**)&a3,  g_a3);
    cudaGetSymbolAddress((void**)&a4,  g_a4);
    cudaGetSymbolAddress((void**)&a5,  g_a5);
    cudaGetSymbolAddress((void**)&wb2, g_wb2);
    cudaGetSymbolAddress((void**)&wb3, g_wb3);
    cudaGetSymbolAddress((void**)&wb4, g_wb4);
    cudaGetSymbolAddress((void**)&wb5, g_wb5);
    cudaGetSymbolAddress((void**)&wb6, g_wb6);
    cudaGetSymbolAddress((void**)&h6,  g_h6);
    cudaGetSymbolAddress((void**)&corr, g_corr);

    int cins[5]  = {128,128,256,256,512};
    int couts[5] = {128,256,256,512,512};

    // pack
    PackArgs pa;
    pa.w[0]=w2; pa.w[1]=w3; pa.w[2]=w4; pa.w[3]=w5; pa.w[4]=w6;
    pa.wb[0]=wb2; pa.wb[1]=wb3; pa.wb[2]=wb4; pa.wb[3]=wb5; pa.wb[4]=wb6;
    {
        int acc = 0;
        for (int l = 0; l < 5; l++) {
            pa.Cin[l] = cins[l]; pa.Cout[l] = couts[l];
            pa.wstart[l] = acc;
            acc += 9*(cins[l]>>5)*(couts[l]>>5);
        }
        pa.wstart[5] = acc;
        pack_all_kernel<<<(acc*32 + 255)/256, 256>>>(pa);
    }

    // edge-correction precompute
    CorrArgs ca;
    ca.wb[0]=wb2; ca.wb[1]=wb3; ca.wb[2]=wb4; ca.wb[3]=wb5; ca.wb[4]=wb6;
    int cbases[5];
    {
        int ob = 0, cb = 0;
        for (int l = 0; l < 5; l++) {
            ca.CW[l] = cins[l]>>5; ca.Cout[l] = couts[l];
            ca.obase[l] = ob; ca.cbase[l] = cb; cbases[l] = cb;
            ob += couts[l]; cb += 8*couts[l];
        }
        ca.obase[5] = ob;
        corr_kernel<<<(ob + 255)/256, 256>>>(ca, corr);
    }

    conv1_kernel<<<dim3(32, BATCH), 128>>>(x, w1, b1, s1, bb1, a1);

    // L2: CW=4, 32x32, Cout=128, POOL  -> 16x8 tiles
    bconv3_kernel<4, 32, 32, 128, 128, true,  false>
        <<<dim3(16*8, BATCH, 1), 128>>>(a1, wb2, s2, bb2, corr+cbases[0], a2, nullptr);
    // L3: CW=4, 16x16, Cout=256, plain -> 16x2 tiles
    bconv3_kernel<4, 16, 16, 256, 256, false, false>
        <<<dim3(16*2, BATCH, 1), 256>>>(a2, wb3, s3, bb3, corr+cbases[1], a3, nullptr);
    // L4: CW=8, 16x16, Cout=256, POOL  -> 8x4 tiles
    bconv3_kernel<8, 16, 16, 256, 256, true,  false>
        <<<dim3(8*4, BATCH, 1), 256>>>(a3, wb4, s4, bb4, corr+cbases[2], a4, nullptr);
    // L5: CW=8, 8x8, Cout=512, plain   -> 8x1 tiles, z-split 2
    bconv3_kernel<8, 8, 8, 512, 256, false, false>
        <<<dim3(8*1, BATCH, 2), 256>>>(a4, wb5, s5, bb5, corr+cbases[3], a5, nullptr);
    // L6: CW=16, 8x8, Cout=512, POOL, float out -> 4x2 tiles, z-split 2
    bconv3_kernel<16, 8, 8, 512, 256, true, true>
        <<<dim3(4*2, BATCH, 2), 256>>>(a5, wb6, s6, bb6, corr+cbases[4], nullptr, h6);

    dense_softmax_kernel<<<BATCH*4*4, 32>>>(h6, dw, db, (float*)d_out);
}